// round 10
// baseline (speedup 1.0000x reference)
#include <cuda_runtime.h>

// TFLoudnessLoss: multi-band (8) loudness difference with softmax weighting.
// Four-step FFT:  n = n1 + 256*n2,  k = k2 + 625*k1   (L = 160000 = 256*625)
// Packing: z_s = xw[s] + i*xo[s] (8 packed signals). Band mask is conjugate-
// symmetric, so IFFT(mask_b * Z) = r_w + i*r_o directly (both real).
// Band structure: with k1 = j + 16 r, for k2>=1 band(k2+625*k1) = r<8 ? r : 15-r.
// inv2: each 25-pt IDFT done as two radix-5 passes on in-place-safe shared
// slots (slot map phi(m) = 5*(m%5) + m/5), ~10 live regs instead of ~100.

#define LTOT 160000
#define NBLK 156
#define NCH  155
#define NDIFF (8*8*155)
#define NBS 128            /* 8 bands x 16 signals (w:0-7, o:8-15) */
#define NPIPE 64           /* 8 bands x 8 packed signals */
#define NG2  52            /* inv2 n1-groups: 52*5 >= 256 */

__device__ float2 d_W[LTOT];              // e^{-2*pi*i*m/L}
__device__ float2 d_W16[16];
__device__ float2 d_W25[25];
__device__ float2 d_spec[8*LTOT];         // packed spectra Z [s][k2*256+k1]
__device__ float2 d_work[8*LTOT];         // fwd intermediate [s][k2*256+n1]
__device__ float2 d_work8[(size_t)NPIPE*LTOT];  // inv intermediate [b*8+s][n1*625+k2]
__device__ float  d_P[NBS*NBLK*NG2];      // partial block energies [bs][jb][g]
__device__ float  d_blk[NBS*NBLK];

__device__ __forceinline__ float2 cmulf(float2 a, float2 b){
  return make_float2(fmaf(a.x,b.x,-a.y*b.y), fmaf(a.x,b.y,a.y*b.x));
}
__device__ __forceinline__ float2 cadd(float2 a,float2 b){return make_float2(a.x+b.x,a.y+b.y);}
__device__ __forceinline__ float2 csub(float2 a,float2 b){return make_float2(a.x-b.x,a.y-b.y);}

__global__ void k_genW(){
  int m = blockIdx.x*blockDim.x + threadIdx.x;
  if (m < LTOT){
    float t = (float)((double)m / 80000.0);   // 2m/L
    float s, c;
    sincospif(t, &s, &c);
    d_W[m] = make_float2(c, -s);
  }
  if (blockIdx.x == 0 && threadIdx.x < 25){
    int q = threadIdx.x;
    if (q < 16){
      float s, c; sincospif(2.f*q/16.f, &s, &c);
      d_W16[q] = make_float2(c, -s);
    }
    float s, c; sincospif(2.f*q/25.f, &s, &c);
    d_W25[q] = make_float2(c, -s);
  }
}

template<int SIGN>
__device__ __forceinline__ void dft5(float2 v[5]){
  const float C1 = 0.30901699437494745f;
  const float S1 = 0.95105651629515353f;
  const float C2 = -0.80901699437494745f;
  const float S2 = 0.58778525229247314f;
  float2 w1 = make_float2(C1,  SIGN*S1);
  float2 w2 = make_float2(C2,  SIGN*S2);
  float2 w3 = make_float2(C2, -SIGN*S2);
  float2 w4 = make_float2(C1, -SIGN*S1);
  float2 o0 = cadd(cadd(v[0],v[1]), cadd(cadd(v[2],v[3]),v[4]));
  float2 o1 = cadd(v[0], cadd(cadd(cmulf(v[1],w1),cmulf(v[2],w2)), cadd(cmulf(v[3],w3),cmulf(v[4],w4))));
  float2 o2 = cadd(v[0], cadd(cadd(cmulf(v[1],w2),cmulf(v[2],w4)), cadd(cmulf(v[3],w1),cmulf(v[4],w3))));
  float2 o3 = cadd(v[0], cadd(cadd(cmulf(v[1],w3),cmulf(v[2],w1)), cadd(cmulf(v[3],w4),cmulf(v[4],w2))));
  float2 o4 = cadd(v[0], cadd(cadd(cmulf(v[1],w4),cmulf(v[2],w3)), cadd(cmulf(v[3],w2),cmulf(v[4],w1))));
  v[0]=o0; v[1]=o1; v[2]=o2; v[3]=o3; v[4]=o4;
}

template<int SIGN>
__device__ __forceinline__ void dft4(float2 v[4]){
  float2 s02 = cadd(v[0],v[2]), d02 = csub(v[0],v[2]);
  float2 s13 = cadd(v[1],v[3]), d13 = csub(v[1],v[3]);
  float2 id13 = make_float2(-d13.y, d13.x);
  float2 o0 = cadd(s02, s13);
  float2 o2 = csub(s02, s13);
  float2 o1, o3;
  if (SIGN < 0){ o1 = csub(d02, id13); o3 = cadd(d02, id13); }
  else         { o1 = cadd(d02, id13); o3 = csub(d02, id13); }
  v[0]=o0; v[1]=o1; v[2]=o2; v[3]=o3;
}

// ---------------- shared-memory Stockham FFTs (forward path) ----------------

template<int SIGN>
__device__ void fft625(float2* __restrict__ A, float2* __restrict__ B, int lane){
  float2* src = A; float2* dst = B;
  int Ns = 1;
  #pragma unroll
  for (int t=0;t<4;t++){
    if (lane < 125){
      int j = lane;
      int jNs = j % Ns;
      int f = LTOT/(Ns*5);
      float2 v[5];
      #pragma unroll
      for (int r=0;r<5;r++){
        float2 x = src[j + r*125];
        int m = r*jNs*f;
        if (m){
          float2 w = d_W[m];
          if (SIGN>0) w.y = -w.y;
          x = cmulf(x,w);
        }
        v[r]=x;
      }
      dft5<SIGN>(v);
      int idxD = (j/Ns)*(Ns*5) + jNs;
      #pragma unroll
      for (int r=0;r<5;r++) dst[idxD + r*Ns] = v[r];
    }
    __syncthreads();
    float2* tmp = src; src = dst; dst = tmp;
    Ns *= 5;
  }
}

template<int SIGN>
__device__ void fft256s(float2* __restrict__ A, float2* __restrict__ B, int lane){
  float2* src = A; float2* dst = B;
  int Ns = 1;
  #pragma unroll
  for (int t=0;t<4;t++){
    {
      int j = lane;
      int jNs = j % Ns;
      int f = LTOT/(Ns*4);
      float2 v[4];
      #pragma unroll
      for (int r=0;r<4;r++){
        float2 x = src[j + r*64];
        int m = r*jNs*f;
        if (m){
          float2 w = d_W[m];
          if (SIGN>0) w.y = -w.y;
          x = cmulf(x,w);
        }
        v[r]=x;
      }
      dft4<SIGN>(v);
      int idxD = (j/Ns)*(Ns*4) + jNs;
      #pragma unroll
      for (int r=0;r<4;r++) dst[idxD + r*Ns] = v[r];
    }
    __syncthreads();
    float2* tmp = src; src = dst; dst = tmp;
    Ns *= 4;
  }
}

// ---------------- forward path ----------------

// z = xw + i*xo : 8 packed signals
__global__ void __launch_bounds__(512) k_fwd1(const float* __restrict__ xw, const float* __restrict__ xo){
  __shared__ float2 sh[4][2][625];
  int tid = threadIdx.x;
  int sub = tid >> 7, lane = tid & 127;
  int n1b = blockIdx.x*4;
  int s   = blockIdx.y;             // 0..7
  const float* xa = xw + s*LTOT;
  const float* xb = xo + s*LTOT;
  for (int i = tid; i < 625; i += 512){
    float4 A = *(const float4*)(xa + n1b + 256*i);
    float4 B = *(const float4*)(xb + n1b + 256*i);
    sh[0][0][i] = make_float2(A.x, B.x);
    sh[1][0][i] = make_float2(A.y, B.y);
    sh[2][0][i] = make_float2(A.z, B.z);
    sh[3][0][i] = make_float2(A.w, B.w);
  }
  __syncthreads();
  fft625<-1>(sh[sub][0], sh[sub][1], lane);
  float2* out = d_work + s*LTOT;
  for (int w = tid; w < 2500; w += 512){
    int k2 = w >> 2, sb = w & 3;
    int n1 = n1b + sb;
    float2 v = cmulf(sh[sb][0][k2], d_W[n1*k2]);
    out[k2*256 + n1] = v;
  }
}

__global__ void __launch_bounds__(256) k_fwd2(){
  __shared__ float2 sh[4][2][256];
  int tid = threadIdx.x, sub = tid>>6, lane = tid&63;
  int row = blockIdx.x*4 + sub;            // s*625 + k2, s in [0,8)
  int s = row / 625, k2 = row - s*625;
  const float2* in = d_work + s*LTOT + k2*256;
  for (int i = lane; i < 256; i += 64) sh[sub][0][i] = in[i];
  __syncthreads();
  fft256s<-1>(sh[sub][0], sh[sub][1], lane);
  float2* out = d_spec + s*LTOT + k2*256;
  for (int i = lane; i < 256; i += 64) out[i] = sh[sub][0][i];
}

// ---------------- inverse stage 1: one band-PAIR per block ----------------
// Block: 128 threads = 8 rows (consecutive k2) x 16 lanes.
// Grid: (79 k2-groups, 8 signals, 4 band-pairs) = 2528 blocks.
// Stage-2 IFFT16 as two in-place radix-4 passes on lane-private shared slots.
__global__ void __launch_bounds__(128, 10) k_inv1_all(){
  __shared__ float2 T[8][257];       // ~16.4KB
  __shared__ float2 shW6[256];       // conj W_L^{625*r*j}  [r*16+j]
  __shared__ float2 shAc[8][16];     // conj W_L^{k2*l},    l<16
  __shared__ float2 shBc[8][16];     // conj W_L^{k2*16*h}, h<16
  __shared__ float2 shW16c[16];      // conj W_16
  int tid = threadIdx.x;
  int row = tid >> 4, j = tid & 15;
  int g = blockIdx.x, s = blockIdx.y, pz = blockIdx.z;
  int k2base = g*8;
  const float2* spec = d_spec + s*LTOT;

  if (tid < 16){ float2 w = d_W16[tid]; shW16c[tid] = make_float2(w.x, -w.y); }
  for (int t = tid; t < 256; t += 128){
    int r = t >> 4, jj = t & 15;
    float2 w = d_W[625*r*jj];
    shW6[t] = make_float2(w.x, -w.y);
  }
  {
    int rr = tid >> 4, e = tid & 15;
    int k2l = k2base + rr;
    int k2c = (k2l < 625) ? k2l : 0;
    float2 wa = d_W[k2c * e];
    float2 wb = d_W[k2c * 16 * e];
    shAc[rr][e] = make_float2(wa.x, -wa.y);
    shBc[rr][e] = make_float2(wb.x, -wb.y);
  }

  int k2 = k2base + row;
  bool rowok = (k2 < 625);
  int k2v = rowok ? k2 : 0;
  const float2* srow = spec + k2v*256;
  bool special = (k2v == 0 && rowok);
  __syncthreads();     // tables ready

  float2 acj = shAc[row][j];   // conj W^{k2*j}

  #pragma unroll
  for (int bi = 0; bi < 2; bi++){
    int b = 2*pz + bi;
    // ---- stage 1 (band-dependent, sparse) ----
    if (special){
      unsigned bm = 0;
      #pragma unroll
      for (int r = 0; r < 16; r++){
        int k1 = j + 16*r;
        int bnd = (k1==0) ? 7 : (((k1<=128)? (k1-1) : (255-k1)) >> 4);
        if (bnd == b) bm |= 1u<<r;
      }
      for (int so = 0; so < 16; so++){
        float2 acc = make_float2(0.f,0.f);
        for (int r = 0; r < 16; r++){
          if (bm & (1u<<r)) acc = cadd(acc, cmulf(srow[j+16*r], shW16c[(r*so)&15]));
        }
        T[row][16*j + (so ^ j)] = acc;
      }
    } else {
      float2 lo = srow[j + 16*b];
      float2 hi = srow[j + 240 - 16*b];
      #pragma unroll
      for (int so = 0; so < 16; so++){
        float2 wl = shW16c[(b*so)&15];
        float2 wh = shW16c[((15-b)*so)&15];
        T[row][16*j + (so ^ j)] = cadd(cmulf(lo, wl), cmulf(hi, wh));
      }
    }
    __syncwarp();      // cross-lane transpose within half-warp row

    // ---- stage 2: IFFT16 over r, in-place on lane-private slots ----
    #pragma unroll
    for (int r0 = 0; r0 < 4; r0++){
      float2 v[4];
      #pragma unroll
      for (int r2 = 0; r2 < 4; r2++){
        int r = r0 + 4*r2;
        v[r2] = cmulf(T[row][16*r + (j ^ r)], shW6[r*16 + j]);
      }
      dft4<1>(v);
      #pragma unroll
      for (int k0 = 0; k0 < 4; k0++){
        float2 c = (r0*k0) ? cmulf(v[k0], shW16c[(r0*k0)&15]) : v[k0];
        int sl = 4*k0 + r0;
        T[row][16*sl + (j ^ sl)] = c;
      }
    }
    #pragma unroll
    for (int k0 = 0; k0 < 4; k0++){
      float2 v[4];
      #pragma unroll
      for (int r0 = 0; r0 < 4; r0++){
        int sl = 4*k0 + r0;
        v[r0] = T[row][16*sl + (j ^ sl)];
      }
      dft4<1>(v);
      #pragma unroll
      for (int k1 = 0; k1 < 4; k1++){
        int q = k0 + 4*k1;
        float2 tw = cmulf(acj, shBc[row][q]);   // conj W^{k2*(j+16q)}
        float2 res = cmulf(v[k1], tw);
        int sl = 4*k0 + k1;
        T[row][16*sl + (j ^ sl)] = res;
      }
    }
    __syncthreads();   // all rows final before cross-row coalesced store

    float2* w8 = d_work8 + (size_t)(b*8 + s)*LTOT;
    for (int t = tid; t < 8*256; t += 128){
      int n1 = t >> 3, rr = t & 7;
      int k2w = k2base + rr;
      int q = n1 >> 4;
      int sl = ((q & 3) << 2) | (q >> 2);      // value for q stored at slot 4(q&3)+(q>>2)
      int p = 16*sl + ((n1 & 15) ^ sl);
      if (k2w < 625) w8[n1*625 + k2w] = T[rr][p];
    }
    __syncthreads();   // T reusable by next band
  }
}

// ---------------- inverse stage 2 + energies: 64 (band, packed signal) ----------------
// Block: 128 threads = 5 n1-rows x 25 lanes (125 active). Each thread does a
// 25-pt IDFT twice, each as two radix-5 passes on in-place-safe shared slots.
// phi(m) = 5*(m%5) + m/5 : logical index m lives at slot phi(m).
#define IROWS 5
__global__ void __launch_bounds__(128, 6) k_inv2_all(){
  __shared__ float2 buf[IROWS][25*26];   // 26KB: [row][coord*26 + slot]
  __shared__ float  Psh[2][IROWS][156];
  __shared__ float2 shWL[625];           // conj W_L^{256*r*lane}  [r*25+lane]
  __shared__ float2 shW25c[25];          // conj W_25
  int tid = threadIdx.x;
  int row = tid / 25, lane = tid % 25;
  bool act = (tid < 125);
  int g = blockIdx.x;                // n1 group
  int bs8 = blockIdx.y;              // b*8 + s
  int b = bs8 >> 3, s = bs8 & 7;
  int n1 = g*IROWS + row;
  bool rowok = act && (n1 < 256);

  for (int t = tid; t < 625; t += 128){
    int r = t / 25, la = t - r*25;
    float2 w = d_W[256*r*la];
    shWL[t] = make_float2(w.x, -w.y);
  }
  if (tid < 25){ float2 w = d_W25[tid]; shW25c[tid] = make_float2(w.x, -w.y); }
  __syncthreads();

  int phl = 5*(lane % 5) + lane/5;   // phi(lane)

  // ---- phase 1: first 25-pt IDFT over p (input C[lane + 25p] from global) ----
  if (act){
    const float2* src = d_work8 + (size_t)bs8*LTOT + (size_t)(rowok ? n1 : 0)*625;
    float2* my = &buf[row][lane*26];
    // pass A: over q; write c[r0][k0] at slot r0+5k0
    #pragma unroll
    for (int r0 = 0; r0 < 5; r0++){
      float2 a[5];
      #pragma unroll
      for (int q = 0; q < 5; q++)
        a[q] = rowok ? src[lane + 25*(r0 + 5*q)] : make_float2(0.f,0.f);
      dft5<1>(a);
      #pragma unroll
      for (int k0 = 0; k0 < 5; k0++)
        my[r0 + 5*k0] = (r0*k0) ? cmulf(a[k0], shW25c[r0*k0]) : a[k0];
    }
    // pass B: over r0; y1[k0+5k1] -> slot 5k0+k1  (== phi(m))
    #pragma unroll
    for (int k0 = 0; k0 < 5; k0++){
      float2 a[5];
      #pragma unroll
      for (int r0 = 0; r0 < 5; r0++) a[r0] = my[r0 + 5*k0];
      dft5<1>(a);
      #pragma unroll
      for (int k1 = 0; k1 < 5; k1++) my[5*k0 + k1] = a[k1];
    }
  }
  __syncthreads();

  // ---- phase 2: second 25-pt IDFT over r2 (cross-lane transpose + twiddle) ----
  if (act){
    // pass A: a[q] = y1^{(r2)}[lane] * wL^{r2*lane},  r2 = r0+5q
    #pragma unroll
    for (int r0 = 0; r0 < 5; r0++){
      float2 a[5];
      #pragma unroll
      for (int q = 0; q < 5; q++){
        int r2 = r0 + 5*q;
        a[q] = cmulf(buf[row][r2*26 + phl], shWL[r2*25 + lane]);
      }
      dft5<1>(a);
      #pragma unroll
      for (int k0 = 0; k0 < 5; k0++){
        float2 c = (r0*k0) ? cmulf(a[k0], shW25c[r0*k0]) : a[k0];
        buf[row][(r0 + 5*k0)*26 + phl] = c;
      }
    }
    // pass B: V2[k0+5k1] -> slot (5k0+k1)*26 + phl   (y[n2=lane+25*m2] at phi(m2)*26+phi(lane))
    #pragma unroll
    for (int k0 = 0; k0 < 5; k0++){
      float2 a[5];
      #pragma unroll
      for (int r0 = 0; r0 < 5; r0++) a[r0] = buf[row][(r0 + 5*k0)*26 + phl];
      dft5<1>(a);
      #pragma unroll
      for (int k1 = 0; k1 < 5; k1++) buf[row][(5*k0 + k1)*26 + phl] = a[k1];
    }
  }
  __syncthreads();

  // ---- energies: block jb needs n2 = 4jb..4jb+3; y[n2] at buf[row][phi(n2/25)*26 + phi(n2%25)] ----
  const float invL2 = (1.0f/160000.0f)*(1.0f/160000.0f);
  for (int t = tid; t < IROWS*156; t += 128){
    int rr = t / 156, jb = t - rr*156;
    float er = 0.f, ei = 0.f;
    #pragma unroll
    for (int q = 0; q < 4; q++){
      int n2 = 4*jb + q;
      int la = n2 % 25, m2 = n2 / 25;
      int sl = (5*(m2 % 5) + m2/5)*26 + (5*(la % 5) + la/5);
      float2 y = buf[rr][sl];
      er = fmaf(y.x, y.x, er);
      ei = fmaf(y.y, y.y, ei);
    }
    Psh[0][rr][jb] = er * invL2;
    Psh[1][rr][jb] = ei * invL2;
  }
  __syncthreads();
  int bs1 = b*16 + s;        // watermarked
  int bs2 = b*16 + s + 8;    // original
  for (int t = tid; t < 2*156; t += 128){
    int half = t / 156, jb = t - half*156;
    float sum = ((Psh[half][0][jb] + Psh[half][1][jb]) +
                 (Psh[half][2][jb] + Psh[half][3][jb])) + Psh[half][4][jb];
    int bsx = half ? bs2 : bs1;
    d_P[((size_t)bsx*NBLK + jb)*NG2 + g] = sum;
  }
}

__global__ void k_red_all(){
  int idx = blockIdx.x*blockDim.x + threadIdx.x;
  if (idx < NBS*NBLK){
    const float* p = d_P + (size_t)idx*NG2;
    float sum = 0.f;
    #pragma unroll 4
    for (int i=0;i<NG2;i++) sum += p[i];
    d_blk[idx] = sum;
  }
}

// diffs + softmax(diff).diff in one block (diff array in shared)
__global__ void __launch_bounds__(1024) k_final(float* __restrict__ out){
  __shared__ float sdiff[NDIFF];
  __shared__ float redA[32];
  __shared__ float redB[32];
  int tid = threadIdx.x;
  for (int t = tid; t < NDIFF; t += 1024){
    int s = t / (8*NCH);
    int rem = t - s*(8*NCH);
    int b = rem / NCH, jb = rem - b*NCH;
    float ew = d_blk[(b*16+s)*NBLK + jb]   + d_blk[(b*16+s)*NBLK + jb + 1];
    float eo = d_blk[(b*16+s+8)*NBLK + jb] + d_blk[(b*16+s+8)*NBLK + jb + 1];
    float lw = 10.f*log10f(ew*(1.f/2048.f) + 1e-12f);
    float lo = 10.f*log10f(eo*(1.f/2048.f) + 1e-12f);
    sdiff[t] = lw - lo;
  }
  __syncthreads();
  float m = -1e30f;
  for (int i = tid; i < NDIFF; i += 1024) m = fmaxf(m, sdiff[i]);
  #pragma unroll
  for (int o = 16; o; o >>= 1) m = fmaxf(m, __shfl_xor_sync(~0u, m, o));
  if ((tid & 31) == 0) redA[tid >> 5] = m;
  __syncthreads();
  {
    float v = redA[tid & 31];
    #pragma unroll
    for (int o = 16; o; o >>= 1) v = fmaxf(v, __shfl_xor_sync(~0u, v, o));
    m = v;                              // full max in every thread
  }
  __syncthreads();
  float se = 0.f, sw = 0.f;
  for (int i = tid; i < NDIFF; i += 1024){
    float d = sdiff[i];
    float e = expf(d - m);
    se += e;
    sw = fmaf(e, d, sw);
  }
  #pragma unroll
  for (int o = 16; o; o >>= 1){
    se += __shfl_xor_sync(~0u, se, o);
    sw += __shfl_xor_sync(~0u, sw, o);
  }
  if ((tid & 31) == 0){ redA[tid >> 5] = se; redB[tid >> 5] = sw; }
  __syncthreads();
  if (tid == 0){
    float s1 = 0.f, s2 = 0.f;
    #pragma unroll
    for (int i = 0; i < 32; i++){ s1 += redA[i]; s2 += redB[i]; }
    out[0] = s2 / s1;
  }
}

extern "C" void kernel_launch(void* const* d_in, const int* in_sizes, int n_in,
                              void* d_out, int out_size){
  const float* xw = (const float*)d_in[0];
  const float* xo = (const float*)d_in[1];
  float* out = (float*)d_out;

  k_genW<<<(LTOT+255)/256, 256>>>();
  k_fwd1<<<dim3(64,8), 512>>>(xw, xo);
  k_fwd2<<<1250, 256>>>();
  k_inv1_all<<<dim3(79,8,4), 128>>>();     // 79*8 = 632 >= 625 k2 rows; 4 band-pairs
  k_inv2_all<<<dim3(NG2,NPIPE), 128>>>();  // 52*5 = 260 >= 256 n1 rows
  k_red_all<<<(NBS*NBLK+255)/256, 256>>>();
  k_final<<<1, 1024>>>(out);
}

// round 11
// speedup vs baseline: 1.0610x; 1.0610x over previous
#include <cuda_runtime.h>

// TFLoudnessLoss: multi-band (8) loudness difference with softmax weighting.
// Four-step FFT:  n = n1 + 256*n2,  k = k2 + 625*k1   (L = 160000 = 256*625)
// Packing: z_s = xw[s] + i*xo[s] (8 packed signals). Band mask is conjugate-
// symmetric, so IFFT(mask_b * Z) = r_w + i*r_o directly (both real).
// Band structure: with k1 = j + 16 r, for k2>=1 band(k2+625*k1) = r<8 ? r : 15-r.
// This round: inverse stage split into 4 independent band-pair chains run on
// 4 concurrent streams (fork/join with timing-disabled events, capture-legal).

#define LTOT 160000
#define NBLK 156
#define NCH  155
#define NDIFF (8*8*155)
#define NBS 128            /* 8 bands x 16 signals (w:0-7, o:8-15) */
#define NPIPE 64           /* 8 bands x 8 packed signals */
#define NG2  52            /* inv2 n1-groups: 52*5 >= 260 >= 256 */

__device__ float2 d_W[LTOT];              // e^{-2*pi*i*m/L}
__device__ float2 d_W16[16];
__device__ float2 d_W25[25];
__device__ float2 d_spec[8*LTOT];         // packed spectra Z [s][k2*256+k1]
__device__ float2 d_work[8*LTOT];         // fwd intermediate [s][k2*256+n1]
__device__ float2 d_work8[(size_t)NPIPE*LTOT];  // inv intermediate [b*8+s][n1*625+k2]
__device__ float  d_P[NBS*NBLK*NG2];      // partial block energies [bs][jb][g]
__device__ float  d_blk[NBS*NBLK];

__device__ __forceinline__ float2 cmulf(float2 a, float2 b){
  return make_float2(fmaf(a.x,b.x,-a.y*b.y), fmaf(a.x,b.y,a.y*b.x));
}
__device__ __forceinline__ float2 cadd(float2 a,float2 b){return make_float2(a.x+b.x,a.y+b.y);}
__device__ __forceinline__ float2 csub(float2 a,float2 b){return make_float2(a.x-b.x,a.y-b.y);}

__global__ void k_genW(){
  int m = blockIdx.x*blockDim.x + threadIdx.x;
  if (m < LTOT){
    float t = (float)((double)m / 80000.0);   // 2m/L
    float s, c;
    sincospif(t, &s, &c);
    d_W[m] = make_float2(c, -s);
  }
  if (blockIdx.x == 0 && threadIdx.x < 25){
    int q = threadIdx.x;
    if (q < 16){
      float s, c; sincospif(2.f*q/16.f, &s, &c);
      d_W16[q] = make_float2(c, -s);
    }
    float s, c; sincospif(2.f*q/25.f, &s, &c);
    d_W25[q] = make_float2(c, -s);
  }
}

template<int SIGN>
__device__ __forceinline__ void dft5(float2 v[5]){
  const float C1 = 0.30901699437494745f;
  const float S1 = 0.95105651629515353f;
  const float C2 = -0.80901699437494745f;
  const float S2 = 0.58778525229247314f;
  float2 w1 = make_float2(C1,  SIGN*S1);
  float2 w2 = make_float2(C2,  SIGN*S2);
  float2 w3 = make_float2(C2, -SIGN*S2);
  float2 w4 = make_float2(C1, -SIGN*S1);
  float2 o0 = cadd(cadd(v[0],v[1]), cadd(cadd(v[2],v[3]),v[4]));
  float2 o1 = cadd(v[0], cadd(cadd(cmulf(v[1],w1),cmulf(v[2],w2)), cadd(cmulf(v[3],w3),cmulf(v[4],w4))));
  float2 o2 = cadd(v[0], cadd(cadd(cmulf(v[1],w2),cmulf(v[2],w4)), cadd(cmulf(v[3],w1),cmulf(v[4],w3))));
  float2 o3 = cadd(v[0], cadd(cadd(cmulf(v[1],w3),cmulf(v[2],w1)), cadd(cmulf(v[3],w4),cmulf(v[4],w2))));
  float2 o4 = cadd(v[0], cadd(cadd(cmulf(v[1],w4),cmulf(v[2],w3)), cadd(cmulf(v[3],w2),cmulf(v[4],w1))));
  v[0]=o0; v[1]=o1; v[2]=o2; v[3]=o3; v[4]=o4;
}

template<int SIGN>
__device__ __forceinline__ void dft4(float2 v[4]){
  float2 s02 = cadd(v[0],v[2]), d02 = csub(v[0],v[2]);
  float2 s13 = cadd(v[1],v[3]), d13 = csub(v[1],v[3]);
  float2 id13 = make_float2(-d13.y, d13.x);
  float2 o0 = cadd(s02, s13);
  float2 o2 = csub(s02, s13);
  float2 o1, o3;
  if (SIGN < 0){ o1 = csub(d02, id13); o3 = cadd(d02, id13); }
  else         { o1 = cadd(d02, id13); o3 = csub(d02, id13); }
  v[0]=o0; v[1]=o1; v[2]=o2; v[3]=o3;
}

// inverse DFT25 using conj-W25 table in shared
__device__ __forceinline__ void dft25i_sh(float2 v[25], const float2* __restrict__ w25c){
  float2 t[25];
  #pragma unroll
  for (int r0=0;r0<5;r0++){
    float2 a[5] = {v[r0], v[r0+5], v[r0+10], v[r0+15], v[r0+20]};
    dft5<1>(a);
    #pragma unroll
    for (int k0=0;k0<5;k0++)
      t[r0*5+k0] = (r0*k0) ? cmulf(a[k0], w25c[r0*k0]) : a[k0];
  }
  #pragma unroll
  for (int k0=0;k0<5;k0++){
    float2 b[5] = {t[k0], t[5+k0], t[10+k0], t[15+k0], t[20+k0]};
    dft5<1>(b);
    #pragma unroll
    for (int k1=0;k1<5;k1++) v[k0+5*k1] = b[k1];
  }
}

// ---------------- shared-memory Stockham FFTs (forward path) ----------------

template<int SIGN>
__device__ void fft625(float2* __restrict__ A, float2* __restrict__ B, int lane){
  float2* src = A; float2* dst = B;
  int Ns = 1;
  #pragma unroll
  for (int t=0;t<4;t++){
    if (lane < 125){
      int j = lane;
      int jNs = j % Ns;
      int f = LTOT/(Ns*5);
      float2 v[5];
      #pragma unroll
      for (int r=0;r<5;r++){
        float2 x = src[j + r*125];
        int m = r*jNs*f;
        if (m){
          float2 w = d_W[m];
          if (SIGN>0) w.y = -w.y;
          x = cmulf(x,w);
        }
        v[r]=x;
      }
      dft5<SIGN>(v);
      int idxD = (j/Ns)*(Ns*5) + jNs;
      #pragma unroll
      for (int r=0;r<5;r++) dst[idxD + r*Ns] = v[r];
    }
    __syncthreads();
    float2* tmp = src; src = dst; dst = tmp;
    Ns *= 5;
  }
}

template<int SIGN>
__device__ void fft256s(float2* __restrict__ A, float2* __restrict__ B, int lane){
  float2* src = A; float2* dst = B;
  int Ns = 1;
  #pragma unroll
  for (int t=0;t<4;t++){
    {
      int j = lane;
      int jNs = j % Ns;
      int f = LTOT/(Ns*4);
      float2 v[4];
      #pragma unroll
      for (int r=0;r<4;r++){
        float2 x = src[j + r*64];
        int m = r*jNs*f;
        if (m){
          float2 w = d_W[m];
          if (SIGN>0) w.y = -w.y;
          x = cmulf(x,w);
        }
        v[r]=x;
      }
      dft4<SIGN>(v);
      int idxD = (j/Ns)*(Ns*4) + jNs;
      #pragma unroll
      for (int r=0;r<4;r++) dst[idxD + r*Ns] = v[r];
    }
    __syncthreads();
    float2* tmp = src; src = dst; dst = tmp;
    Ns *= 4;
  }
}

// ---------------- forward path ----------------

// z = xw + i*xo : 8 packed signals
__global__ void __launch_bounds__(512) k_fwd1(const float* __restrict__ xw, const float* __restrict__ xo){
  __shared__ float2 sh[4][2][625];
  int tid = threadIdx.x;
  int sub = tid >> 7, lane = tid & 127;
  int n1b = blockIdx.x*4;
  int s   = blockIdx.y;             // 0..7
  const float* xa = xw + s*LTOT;
  const float* xb = xo + s*LTOT;
  for (int w = tid; w < 2500; w += 512){
    int n2 = w >> 2, sb = w & 3;
    int n = n1b + sb + 256*n2;
    sh[sb][0][n2] = make_float2(xa[n], xb[n]);
  }
  __syncthreads();
  fft625<-1>(sh[sub][0], sh[sub][1], lane);
  float2* out = d_work + s*LTOT;
  for (int w = tid; w < 2500; w += 512){
    int k2 = w >> 2, sb = w & 3;
    int n1 = n1b + sb;
    float2 v = cmulf(sh[sb][0][k2], d_W[n1*k2]);
    out[k2*256 + n1] = v;
  }
}

__global__ void __launch_bounds__(256) k_fwd2(){
  __shared__ float2 sh[4][2][256];
  int tid = threadIdx.x, sub = tid>>6, lane = tid&63;
  int row = blockIdx.x*4 + sub;            // s*625 + k2, s in [0,8)
  int s = row / 625, k2 = row - s*625;
  const float2* in = d_work + s*LTOT + k2*256;
  for (int i = lane; i < 256; i += 64) sh[sub][0][i] = in[i];
  __syncthreads();
  fft256s<-1>(sh[sub][0], sh[sub][1], lane);
  float2* out = d_spec + s*LTOT + k2*256;
  for (int i = lane; i < 256; i += 64) out[i] = sh[sub][0][i];
}

// ---------------- inverse stage 1: one band-PAIR per launch (pz arg) ----------------
// Block: 128 threads = 8 rows (consecutive k2) x 16 lanes.
// Grid: (79 k2-groups, 8 signals) per pair.
__global__ void __launch_bounds__(128, 10) k_inv1_all(int pz){
  __shared__ float2 T[8][257];       // ~16.4KB
  __shared__ float2 shW6[256];       // conj W_L^{625*r*j}  [r*16+j]
  __shared__ float2 shAc[8][16];     // conj W_L^{k2*l},    l<16
  __shared__ float2 shBc[8][16];     // conj W_L^{k2*16*h}, h<16
  __shared__ float2 shW16c[16];      // conj W_16
  int tid = threadIdx.x;
  int row = tid >> 4, j = tid & 15;
  int g = blockIdx.x, s = blockIdx.y;
  int k2base = g*8;
  const float2* spec = d_spec + s*LTOT;

  if (tid < 16){ float2 w = d_W16[tid]; shW16c[tid] = make_float2(w.x, -w.y); }
  for (int t = tid; t < 256; t += 128){
    int r = t >> 4, jj = t & 15;
    float2 w = d_W[625*r*jj];
    shW6[t] = make_float2(w.x, -w.y);
  }
  {
    int rr = tid >> 4, e = tid & 15;
    int k2l = k2base + rr;
    int k2c = (k2l < 625) ? k2l : 0;
    float2 wa = d_W[k2c * e];
    float2 wb = d_W[k2c * 16 * e];
    shAc[rr][e] = make_float2(wa.x, -wa.y);
    shBc[rr][e] = make_float2(wb.x, -wb.y);
  }

  int k2 = k2base + row;
  bool rowok = (k2 < 625);
  int k2v = rowok ? k2 : 0;
  const float2* srow = spec + k2v*256;
  bool special = (k2v == 0 && rowok);
  __syncthreads();     // tables ready

  float2 acj = shAc[row][j];   // conj W^{k2*j}

  #pragma unroll
  for (int bi = 0; bi < 2; bi++){
    int b = 2*pz + bi;
    // ---- stage 1 (band-dependent, sparse) ----
    if (special){
      unsigned bm = 0;
      #pragma unroll
      for (int r = 0; r < 16; r++){
        int k1 = j + 16*r;
        int bnd = (k1==0) ? 7 : (((k1<=128)? (k1-1) : (255-k1)) >> 4);
        if (bnd == b) bm |= 1u<<r;
      }
      for (int so = 0; so < 16; so++){
        float2 acc = make_float2(0.f,0.f);
        for (int r = 0; r < 16; r++){
          if (bm & (1u<<r)) acc = cadd(acc, cmulf(srow[j+16*r], shW16c[(r*so)&15]));
        }
        T[row][16*j + (so ^ j)] = acc;
      }
    } else {
      float2 lo = srow[j + 16*b];
      float2 hi = srow[j + 240 - 16*b];
      #pragma unroll
      for (int so = 0; so < 16; so++){
        float2 wl = shW16c[(b*so)&15];
        float2 wh = shW16c[((15-b)*so)&15];
        T[row][16*j + (so ^ j)] = cadd(cmulf(lo, wl), cmulf(hi, wh));
      }
    }
    __syncwarp();      // cross-lane transpose within half-warp row

    // ---- stage 2: IFFT16 over r, in-place on lane-private slots ----
    #pragma unroll
    for (int r0 = 0; r0 < 4; r0++){
      float2 v[4];
      #pragma unroll
      for (int r2 = 0; r2 < 4; r2++){
        int r = r0 + 4*r2;
        v[r2] = cmulf(T[row][16*r + (j ^ r)], shW6[r*16 + j]);
      }
      dft4<1>(v);
      #pragma unroll
      for (int k0 = 0; k0 < 4; k0++){
        float2 c = (r0*k0) ? cmulf(v[k0], shW16c[(r0*k0)&15]) : v[k0];
        int sl = 4*k0 + r0;
        T[row][16*sl + (j ^ sl)] = c;
      }
    }
    #pragma unroll
    for (int k0 = 0; k0 < 4; k0++){
      float2 v[4];
      #pragma unroll
      for (int r0 = 0; r0 < 4; r0++){
        int sl = 4*k0 + r0;
        v[r0] = T[row][16*sl + (j ^ sl)];
      }
      dft4<1>(v);
      #pragma unroll
      for (int k1 = 0; k1 < 4; k1++){
        int q = k0 + 4*k1;
        float2 tw = cmulf(acj, shBc[row][q]);   // conj W^{k2*(j+16q)}
        float2 res = cmulf(v[k1], tw);
        int sl = 4*k0 + k1;
        T[row][16*sl + (j ^ sl)] = res;
      }
    }
    __syncthreads();   // all rows final before cross-row coalesced store

    float2* w8 = d_work8 + (size_t)(b*8 + s)*LTOT;
    for (int t = tid; t < 8*256; t += 128){
      int n1 = t >> 3, rr = t & 7;
      int k2w = k2base + rr;
      int q = n1 >> 4;
      int sl = ((q & 3) << 2) | (q >> 2);      // value for q stored at slot 4(q&3)+(q>>2)
      int p = 16*sl + ((n1 & 15) ^ sl);
      if (k2w < 625) w8[n1*625 + k2w] = T[rr][p];
    }
    __syncthreads();   // T reusable by next band
  }
}

// ---------------- inverse stage 2 + energies: one band-PAIR per launch ----------------
#define IROWS 5
__global__ void __launch_bounds__(128) k_inv2_all(int pair){
  __shared__ float2 buf[IROWS][25*26];
  __shared__ float  Psh[2][IROWS][156];
  __shared__ float2 shWL[625];       // conj W_L^{256*r*lane}  [r*25+lane]
  __shared__ float2 shW25c[25];      // conj W_25
  int tid = threadIdx.x;
  int row = tid / 25, lane = tid % 25;
  bool act = (tid < 125);
  int g = blockIdx.x;                // n1 group
  int bs8 = pair*16 + blockIdx.y;    // b*8 + s
  int b = bs8 >> 3, s = bs8 & 7;
  int n1 = g*IROWS + row;
  bool rowok = act && (n1 < 256);

  for (int t = tid; t < 625; t += 128){
    int r = t / 25, la = t - r*25;
    float2 w = d_W[256*r*la];
    shWL[t] = make_float2(w.x, -w.y);
  }
  if (tid < 25){ float2 w = d_W25[tid]; shW25c[tid] = make_float2(w.x, -w.y); }
  __syncthreads();

  float2 u[25];
  if (act){
    const float2* src = d_work8 + (size_t)bs8*LTOT + (size_t)(rowok ? n1 : 0)*625;
    float2 v[25];
    #pragma unroll
    for (int r=0;r<25;r++) v[r] = rowok ? src[lane + 25*r] : make_float2(0.f,0.f);
    dft25i_sh(v, shW25c);
    #pragma unroll
    for (int r=0;r<25;r++) buf[row][lane*26 + r] = v[r];
  }
  __syncthreads();
  if (act){
    #pragma unroll
    for (int r=0;r<25;r++)
      u[r] = cmulf(buf[row][r*26 + lane], shWL[r*25 + lane]);
    dft25i_sh(u, shW25c);            // y_w + i*y_o at n2 = lane + 25r  (x L)
  }
  __syncthreads();
  float* eR = (float*)&buf[0][0];
  float* eI = eR + IROWS*625;
  const float invL = 1.0f/160000.0f;
  if (act){
    #pragma unroll
    for (int r=0;r<25;r++){
      int n2 = lane + 25*r;
      float yr = u[r].x * invL;
      float yi = u[r].y * invL;
      eR[row*625 + n2] = yr*yr;
      eI[row*625 + n2] = yi*yi;
    }
  }
  __syncthreads();
  for (int t = tid; t < IROWS*156; t += 128){
    int rr = t / 156, jb = t - rr*156;
    const float* e0 = eR + rr*625 + 4*jb;
    const float* e1 = eI + rr*625 + 4*jb;
    Psh[0][rr][jb] = (e0[0] + e0[1]) + (e0[2] + e0[3]);
    Psh[1][rr][jb] = (e1[0] + e1[1]) + (e1[2] + e1[3]);
  }
  __syncthreads();
  int bs1 = b*16 + s;        // watermarked
  int bs2 = b*16 + s + 8;    // original
  for (int t = tid; t < 2*156; t += 128){
    int half = t / 156, jb = t - half*156;
    float sum = ((Psh[half][0][jb] + Psh[half][1][jb]) +
                 (Psh[half][2][jb] + Psh[half][3][jb])) + Psh[half][4][jb];
    int bsx = half ? bs2 : bs1;
    d_P[((size_t)bsx*NBLK + jb)*NG2 + g] = sum;
  }
}

// Reduce partials over g for one band-pair: bs in [32*pair, 32*pair+32).
__global__ void k_red_pair(int pair){
  int t = blockIdx.x*blockDim.x + threadIdx.x;
  if (t < 32*NBLK){
    int bs = pair*32 + t/NBLK, jb = t - (t/NBLK)*NBLK;
    const float* p = d_P + ((size_t)bs*NBLK + jb)*NG2;
    float sum = 0.f;
    #pragma unroll 4
    for (int i=0;i<NG2;i++) sum += p[i];
    d_blk[bs*NBLK + jb] = sum;
  }
}

// diffs + softmax(diff).diff in one block (diff array in shared)
__global__ void __launch_bounds__(1024) k_final(float* __restrict__ out){
  __shared__ float sdiff[NDIFF];
  __shared__ float redA[32];
  __shared__ float redB[32];
  int tid = threadIdx.x;
  for (int t = tid; t < NDIFF; t += 1024){
    int s = t / (8*NCH);
    int rem = t - s*(8*NCH);
    int b = rem / NCH, jb = rem - b*NCH;
    float ew = d_blk[(b*16+s)*NBLK + jb]   + d_blk[(b*16+s)*NBLK + jb + 1];
    float eo = d_blk[(b*16+s+8)*NBLK + jb] + d_blk[(b*16+s+8)*NBLK + jb + 1];
    float lw = 10.f*log10f(ew*(1.f/2048.f) + 1e-12f);
    float lo = 10.f*log10f(eo*(1.f/2048.f) + 1e-12f);
    sdiff[t] = lw - lo;
  }
  __syncthreads();
  float m = -1e30f;
  for (int i = tid; i < NDIFF; i += 1024) m = fmaxf(m, sdiff[i]);
  #pragma unroll
  for (int o = 16; o; o >>= 1) m = fmaxf(m, __shfl_xor_sync(~0u, m, o));
  if ((tid & 31) == 0) redA[tid >> 5] = m;
  __syncthreads();
  {
    float v = redA[tid & 31];
    #pragma unroll
    for (int o = 16; o; o >>= 1) v = fmaxf(v, __shfl_xor_sync(~0u, v, o));
    m = v;                              // full max in every thread
  }
  __syncthreads();
  float se = 0.f, sw = 0.f;
  for (int i = tid; i < NDIFF; i += 1024){
    float d = sdiff[i];
    float e = expf(d - m);
    se += e;
    sw = fmaf(e, d, sw);
  }
  #pragma unroll
  for (int o = 16; o; o >>= 1){
    se += __shfl_xor_sync(~0u, se, o);
    sw += __shfl_xor_sync(~0u, sw, o);
  }
  if ((tid & 31) == 0){ redA[tid >> 5] = se; redB[tid >> 5] = sw; }
  __syncthreads();
  if (tid == 0){
    float s1 = 0.f, s2 = 0.f;
    #pragma unroll
    for (int i = 0; i < 32; i++){ s1 += redA[i]; s2 += redB[i]; }
    out[0] = s2 / s1;
  }
}

// ---------------- streams (created once at program load; no device mem) ----------------
struct HxStreams {
  cudaStream_t st[4];
  cudaEvent_t  evF;
  cudaEvent_t  evJ[4];
  bool ok;
  HxStreams(){
    ok = true;
    for (int i = 0; i < 4; i++)
      if (cudaStreamCreateWithFlags(&st[i], cudaStreamNonBlocking) != cudaSuccess) ok = false;
    if (cudaEventCreateWithFlags(&evF, cudaEventDisableTiming) != cudaSuccess) ok = false;
    for (int i = 0; i < 4; i++)
      if (cudaEventCreateWithFlags(&evJ[i], cudaEventDisableTiming) != cudaSuccess) ok = false;
  }
};
static HxStreams g_hx;

extern "C" void kernel_launch(void* const* d_in, const int* in_sizes, int n_in,
                              void* d_out, int out_size){
  const float* xw = (const float*)d_in[0];
  const float* xo = (const float*)d_in[1];
  float* out = (float*)d_out;

  k_genW<<<(LTOT+255)/256, 256>>>();
  k_fwd1<<<dim3(64,8), 512>>>(xw, xo);
  k_fwd2<<<1250, 256>>>();

  if (g_hx.ok){
    cudaEventRecord(g_hx.evF, 0);
    for (int p = 0; p < 4; p++){
      cudaStreamWaitEvent(g_hx.st[p], g_hx.evF, 0);
      k_inv1_all<<<dim3(79,8), 128, 0, g_hx.st[p]>>>(p);
      k_inv2_all<<<dim3(NG2,16), 128, 0, g_hx.st[p]>>>(p);
      k_red_pair<<<(32*NBLK+255)/256, 256, 0, g_hx.st[p]>>>(p);
      cudaEventRecord(g_hx.evJ[p], g_hx.st[p]);
    }
    for (int p = 0; p < 4; p++)
      cudaStreamWaitEvent(0, g_hx.evJ[p], 0);
  } else {
    for (int p = 0; p < 4; p++){
      k_inv1_all<<<dim3(79,8), 128>>>(p);
      k_inv2_all<<<dim3(NG2,16), 128>>>(p);
      k_red_pair<<<(32*NBLK+255)/256, 256>>>(p);
    }
  }
  k_final<<<1, 1024>>>(out);
}

// round 12
// speedup vs baseline: 1.2189x; 1.1488x over previous
#include <cuda_runtime.h>

// TFLoudnessLoss: multi-band (8) loudness difference with softmax weighting.
// Four-step FFT:  n = n1 + 256*n2,  k = k2 + 625*k1   (L = 160000 = 256*625)
// Packing: z_s = xw[s] + i*xo[s] (8 packed signals). Band mask is conjugate-
// symmetric, so IFFT(mask_b * Z) = r_w + i*r_o directly (both real).
// Band structure: with k1 = j + 16 r, for k2>=1 band(k2+625*k1) = r<8 ? r : 15-r.
// This round: fwd2 (FFT256 over n1) and inv1 (mask + IFFT256 over k1) fused;
// the spectrum row never leaves shared memory (d_spec eliminated).

#define LTOT 160000
#define NBLK 156
#define NCH  155
#define NDIFF (8*8*155)
#define NBS 128            /* 8 bands x 16 signals (w:0-7, o:8-15) */
#define NPIPE 64           /* 8 bands x 8 packed signals */
#define NG2  52            /* inv2 n1-groups: 52*5 >= 260 >= 256 */

__device__ float2 d_W[LTOT];              // e^{-2*pi*i*m/L}
__device__ float2 d_W16[16];
__device__ float2 d_W25[25];
__device__ float2 d_work[8*LTOT];         // fwd intermediate [s][k2*256+n1]
__device__ float2 d_work8[(size_t)NPIPE*LTOT];  // inv intermediate [b*8+s][n1*625+k2]
__device__ float  d_P[NBS*NBLK*NG2];      // partial block energies [bs][jb][g]
__device__ float  d_blk[NBS*NBLK];

__device__ __forceinline__ float2 cmulf(float2 a, float2 b){
  return make_float2(fmaf(a.x,b.x,-a.y*b.y), fmaf(a.x,b.y,a.y*b.x));
}
__device__ __forceinline__ float2 cadd(float2 a,float2 b){return make_float2(a.x+b.x,a.y+b.y);}
__device__ __forceinline__ float2 csub(float2 a,float2 b){return make_float2(a.x-b.x,a.y-b.y);}

__global__ void k_genW(){
  int m = blockIdx.x*blockDim.x + threadIdx.x;
  if (m < LTOT){
    float t = (float)((double)m / 80000.0);   // 2m/L
    float s, c;
    sincospif(t, &s, &c);
    d_W[m] = make_float2(c, -s);
  }
  if (blockIdx.x == 0 && threadIdx.x < 25){
    int q = threadIdx.x;
    if (q < 16){
      float s, c; sincospif(2.f*q/16.f, &s, &c);
      d_W16[q] = make_float2(c, -s);
    }
    float s, c; sincospif(2.f*q/25.f, &s, &c);
    d_W25[q] = make_float2(c, -s);
  }
}

template<int SIGN>
__device__ __forceinline__ void dft5(float2 v[5]){
  const float C1 = 0.30901699437494745f;
  const float S1 = 0.95105651629515353f;
  const float C2 = -0.80901699437494745f;
  const float S2 = 0.58778525229247314f;
  float2 w1 = make_float2(C1,  SIGN*S1);
  float2 w2 = make_float2(C2,  SIGN*S2);
  float2 w3 = make_float2(C2, -SIGN*S2);
  float2 w4 = make_float2(C1, -SIGN*S1);
  float2 o0 = cadd(cadd(v[0],v[1]), cadd(cadd(v[2],v[3]),v[4]));
  float2 o1 = cadd(v[0], cadd(cadd(cmulf(v[1],w1),cmulf(v[2],w2)), cadd(cmulf(v[3],w3),cmulf(v[4],w4))));
  float2 o2 = cadd(v[0], cadd(cadd(cmulf(v[1],w2),cmulf(v[2],w4)), cadd(cmulf(v[3],w1),cmulf(v[4],w3))));
  float2 o3 = cadd(v[0], cadd(cadd(cmulf(v[1],w3),cmulf(v[2],w1)), cadd(cmulf(v[3],w4),cmulf(v[4],w2))));
  float2 o4 = cadd(v[0], cadd(cadd(cmulf(v[1],w4),cmulf(v[2],w3)), cadd(cmulf(v[3],w2),cmulf(v[4],w1))));
  v[0]=o0; v[1]=o1; v[2]=o2; v[3]=o3; v[4]=o4;
}

template<int SIGN>
__device__ __forceinline__ void dft4(float2 v[4]){
  float2 s02 = cadd(v[0],v[2]), d02 = csub(v[0],v[2]);
  float2 s13 = cadd(v[1],v[3]), d13 = csub(v[1],v[3]);
  float2 id13 = make_float2(-d13.y, d13.x);
  float2 o0 = cadd(s02, s13);
  float2 o2 = csub(s02, s13);
  float2 o1, o3;
  if (SIGN < 0){ o1 = csub(d02, id13); o3 = cadd(d02, id13); }
  else         { o1 = cadd(d02, id13); o3 = csub(d02, id13); }
  v[0]=o0; v[1]=o1; v[2]=o2; v[3]=o3;
}

// inverse DFT25 using conj-W25 table in shared
__device__ __forceinline__ void dft25i_sh(float2 v[25], const float2* __restrict__ w25c){
  float2 t[25];
  #pragma unroll
  for (int r0=0;r0<5;r0++){
    float2 a[5] = {v[r0], v[r0+5], v[r0+10], v[r0+15], v[r0+20]};
    dft5<1>(a);
    #pragma unroll
    for (int k0=0;k0<5;k0++)
      t[r0*5+k0] = (r0*k0) ? cmulf(a[k0], w25c[r0*k0]) : a[k0];
  }
  #pragma unroll
  for (int k0=0;k0<5;k0++){
    float2 b[5] = {t[k0], t[5+k0], t[10+k0], t[15+k0], t[20+k0]};
    dft5<1>(b);
    #pragma unroll
    for (int k1=0;k1<5;k1++) v[k0+5*k1] = b[k1];
  }
}

// ---------------- shared-memory Stockham FFTs ----------------

template<int SIGN>
__device__ void fft625(float2* __restrict__ A, float2* __restrict__ B, int lane){
  float2* src = A; float2* dst = B;
  int Ns = 1;
  #pragma unroll
  for (int t=0;t<4;t++){
    if (lane < 125){
      int j = lane;
      int jNs = j % Ns;
      int f = LTOT/(Ns*5);
      float2 v[5];
      #pragma unroll
      for (int r=0;r<5;r++){
        float2 x = src[j + r*125];
        int m = r*jNs*f;
        if (m){
          float2 w = d_W[m];
          if (SIGN>0) w.y = -w.y;
          x = cmulf(x,w);
        }
        v[r]=x;
      }
      dft5<SIGN>(v);
      int idxD = (j/Ns)*(Ns*5) + jNs;
      #pragma unroll
      for (int r=0;r<5;r++) dst[idxD + r*Ns] = v[r];
    }
    __syncthreads();
    float2* tmp = src; src = dst; dst = tmp;
    Ns *= 5;
  }
}

template<int SIGN>
__device__ void fft256s(float2* __restrict__ A, float2* __restrict__ B, int lane){
  float2* src = A; float2* dst = B;
  int Ns = 1;
  #pragma unroll
  for (int t=0;t<4;t++){
    {
      int j = lane;
      int jNs = j % Ns;
      int f = LTOT/(Ns*4);
      float2 v[4];
      #pragma unroll
      for (int r=0;r<4;r++){
        float2 x = src[j + r*64];
        int m = r*jNs*f;
        if (m){
          float2 w = d_W[m];
          if (SIGN>0) w.y = -w.y;
          x = cmulf(x,w);
        }
        v[r]=x;
      }
      dft4<SIGN>(v);
      int idxD = (j/Ns)*(Ns*4) + jNs;
      #pragma unroll
      for (int r=0;r<4;r++) dst[idxD + r*Ns] = v[r];
    }
    __syncthreads();
    float2* tmp = src; src = dst; dst = tmp;
    Ns *= 4;
  }
}

// ---------------- forward stage 1 ----------------

// z = xw + i*xo : 8 packed signals
__global__ void __launch_bounds__(512) k_fwd1(const float* __restrict__ xw, const float* __restrict__ xo){
  __shared__ float2 sh[4][2][625];
  int tid = threadIdx.x;
  int sub = tid >> 7, lane = tid & 127;
  int n1b = blockIdx.x*4;
  int s   = blockIdx.y;             // 0..7
  const float* xa = xw + s*LTOT;
  const float* xb = xo + s*LTOT;
  for (int w = tid; w < 2500; w += 512){
    int n2 = w >> 2, sb = w & 3;
    int n = n1b + sb + 256*n2;
    sh[sb][0][n2] = make_float2(xa[n], xb[n]);
  }
  __syncthreads();
  fft625<-1>(sh[sub][0], sh[sub][1], lane);
  float2* out = d_work + s*LTOT;
  for (int w = tid; w < 2500; w += 512){
    int k2 = w >> 2, sb = w & 3;
    int n1 = n1b + sb;
    float2 v = cmulf(sh[sb][0][k2], d_W[n1*k2]);
    out[k2*256 + n1] = v;
  }
}

// ---------------- fused forward stage 2 + inverse stage 1 ----------------
// Block: 256 threads. FFT phase: 4 k2-rows x 64 lanes (forward FFT256 over n1).
// Inverse phase: 4 rows x 4 band-groups x 16 lanes; group bg handles bands
// 2bg and 2bg+1 sequentially with the in-place IFFT16 slot scheme.
// Grid: (157 k2-groups, 8 signals).
__global__ void __launch_bounds__(256) k_f2i1(){
  __shared__ float2 sh[4][2][256];   // 16KB fft buffers; X stays in sh[row][0]
  __shared__ float2 T[16][257];      // 32.9KB: [row*4 + grp]
  __shared__ float2 shW6[256];       // conj W_L^{625*r*j}  [r*16+j]
  __shared__ float2 shAc[4][16];     // conj W_L^{k2*l},    l<16
  __shared__ float2 shBc[4][16];     // conj W_L^{k2*16*h}, h<16
  __shared__ float2 shW16c[16];      // conj W_16
  int tid = threadIdx.x;
  int sub = tid >> 6, lane = tid & 63;
  int g = blockIdx.x, s = blockIdx.y;
  int k2 = g*4 + sub;
  bool rowok = (k2 < 625);
  int k2v = rowok ? k2 : 0;

  // tables
  if (tid < 16){ float2 w = d_W16[tid]; shW16c[tid] = make_float2(w.x, -w.y); }
  if (tid >= 32 && tid < 96){
    int t2 = tid - 32;
    int rr = t2 >> 4, e = t2 & 15;
    int k2l = g*4 + rr;
    int k2c = (k2l < 625) ? k2l : 0;
    float2 wa = d_W[k2c * e];
    shAc[rr][e] = make_float2(wa.x, -wa.y);
  }
  if (tid >= 96 && tid < 160){
    int t2 = tid - 96;
    int rr = t2 >> 4, e = t2 & 15;
    int k2l = g*4 + rr;
    int k2c = (k2l < 625) ? k2l : 0;
    float2 wb = d_W[k2c * 16 * e];
    shBc[rr][e] = make_float2(wb.x, -wb.y);
  }
  for (int t = tid; t < 256; t += 256){
    int r = t >> 4, jj = t & 15;
    float2 w = d_W[625*r*jj];
    shW6[t] = make_float2(w.x, -w.y);
  }

  // load B[n1] for this k2 row and run forward FFT256 over n1
  const float2* in = d_work + s*LTOT + k2v*256;
  for (int i = lane; i < 256; i += 64) sh[sub][0][i] = in[i];
  __syncthreads();
  fft256s<-1>(sh[sub][0], sh[sub][1], lane);   // X in sh[sub][0]; ends with syncthreads

  // inverse phase thread mapping
  int row = sub;                 // 0..3 (same k2 row)
  int grp = lane >> 4;           // 0..3 band group
  int j   = lane & 15;
  float2* Tb = T[row*4 + grp];
  const float2* Xr = sh[row][0];
  bool special = (k2v == 0 && rowok);
  float2 acj = shAc[row][j];     // conj W^{k2*j}

  #pragma unroll
  for (int bi = 0; bi < 2; bi++){
    int b = 2*grp + bi;
    // ---- stage 1 (band-dependent, sparse) ----
    if (special){
      unsigned bm = 0;
      #pragma unroll
      for (int r = 0; r < 16; r++){
        int k1 = j + 16*r;
        int bnd = (k1==0) ? 7 : (((k1<=128)? (k1-1) : (255-k1)) >> 4);
        if (bnd == b) bm |= 1u<<r;
      }
      for (int so = 0; so < 16; so++){
        float2 acc = make_float2(0.f,0.f);
        for (int r = 0; r < 16; r++){
          if (bm & (1u<<r)) acc = cadd(acc, cmulf(Xr[j+16*r], shW16c[(r*so)&15]));
        }
        Tb[16*j + (so ^ j)] = acc;
      }
    } else {
      float2 lo = Xr[j + 16*b];
      float2 hi = Xr[j + 240 - 16*b];
      #pragma unroll
      for (int so = 0; so < 16; so++){
        float2 wl = shW16c[(b*so)&15];
        float2 wh = shW16c[((15-b)*so)&15];
        Tb[16*j + (so ^ j)] = cadd(cmulf(lo, wl), cmulf(hi, wh));
      }
    }
    __syncwarp();      // cross-lane transpose inside the 16-lane group

    // ---- stage 2: IFFT16 over r, in-place on lane-private slots ----
    #pragma unroll
    for (int r0 = 0; r0 < 4; r0++){
      float2 v[4];
      #pragma unroll
      for (int r2 = 0; r2 < 4; r2++){
        int r = r0 + 4*r2;
        v[r2] = cmulf(Tb[16*r + (j ^ r)], shW6[r*16 + j]);
      }
      dft4<1>(v);
      #pragma unroll
      for (int k0 = 0; k0 < 4; k0++){
        float2 c = (r0*k0) ? cmulf(v[k0], shW16c[(r0*k0)&15]) : v[k0];
        int sl = 4*k0 + r0;
        Tb[16*sl + (j ^ sl)] = c;
      }
    }
    #pragma unroll
    for (int k0 = 0; k0 < 4; k0++){
      float2 v[4];
      #pragma unroll
      for (int r0 = 0; r0 < 4; r0++){
        int sl = 4*k0 + r0;
        v[r0] = Tb[16*sl + (j ^ sl)];
      }
      dft4<1>(v);
      #pragma unroll
      for (int k1 = 0; k1 < 4; k1++){
        int q = k0 + 4*k1;
        float2 tw = cmulf(acj, shBc[row][q]);   // conj W^{k2*(j+16q)}
        float2 res = cmulf(v[k1], tw);
        int sl = 4*k0 + k1;
        Tb[16*sl + (j ^ sl)] = res;
      }
    }
    __syncthreads();   // all groups' T final before cooperative store

    // store bands {bi, 2+bi, 4+bi, 6+bi}: 4 bands x 256 n1 x 4 k2
    for (int idx = tid; idx < 4096; idx += 256){
      int bg  = idx >> 10;
      int rem = idx & 1023;
      int n1  = rem >> 2;
      int k2r = rem & 3;
      int k2w = g*4 + k2r;
      if (k2w < 625){
        int b2 = 2*bg + bi;
        int q = n1 >> 4;
        int sl = ((q & 3) << 2) | (q >> 2);
        int p = 16*sl + ((n1 & 15) ^ sl);
        d_work8[(size_t)(b2*8 + s)*LTOT + n1*625 + k2w] = T[k2r*4 + bg][p];
      }
    }
    __syncthreads();   // T reusable in next bi
  }
}

// ---------------- inverse stage 2 + energies: 64 (band, packed signal) ----------------
#define IROWS 5
__global__ void __launch_bounds__(128) k_inv2_all(){
  __shared__ float2 buf[IROWS][25*26];
  __shared__ float  Psh[2][IROWS][156];
  __shared__ float2 shWL[625];       // conj W_L^{256*r*lane}  [r*25+lane]
  __shared__ float2 shW25c[25];      // conj W_25
  int tid = threadIdx.x;
  int row = tid / 25, lane = tid % 25;
  bool act = (tid < 125);
  int g = blockIdx.x;                // n1 group
  int bs8 = blockIdx.y;              // b*8 + s
  int b = bs8 >> 3, s = bs8 & 7;
  int n1 = g*IROWS + row;
  bool rowok = act && (n1 < 256);

  for (int t = tid; t < 625; t += 128){
    int r = t / 25, la = t - r*25;
    float2 w = d_W[256*r*la];
    shWL[t] = make_float2(w.x, -w.y);
  }
  if (tid < 25){ float2 w = d_W25[tid]; shW25c[tid] = make_float2(w.x, -w.y); }
  __syncthreads();

  float2 u[25];
  if (act){
    const float2* src = d_work8 + (size_t)bs8*LTOT + (size_t)(rowok ? n1 : 0)*625;
    float2 v[25];
    #pragma unroll
    for (int r=0;r<25;r++) v[r] = rowok ? src[lane + 25*r] : make_float2(0.f,0.f);
    dft25i_sh(v, shW25c);
    #pragma unroll
    for (int r=0;r<25;r++) buf[row][lane*26 + r] = v[r];
  }
  __syncthreads();
  if (act){
    #pragma unroll
    for (int r=0;r<25;r++)
      u[r] = cmulf(buf[row][r*26 + lane], shWL[r*25 + lane]);
    dft25i_sh(u, shW25c);            // y_w + i*y_o at n2 = lane + 25r  (x L)
  }
  __syncthreads();
  float* eR = (float*)&buf[0][0];
  float* eI = eR + IROWS*625;
  const float invL = 1.0f/160000.0f;
  if (act){
    #pragma unroll
    for (int r=0;r<25;r++){
      int n2 = lane + 25*r;
      float yr = u[r].x * invL;
      float yi = u[r].y * invL;
      eR[row*625 + n2] = yr*yr;
      eI[row*625 + n2] = yi*yi;
    }
  }
  __syncthreads();
  for (int t = tid; t < IROWS*156; t += 128){
    int rr = t / 156, jb = t - rr*156;
    const float* e0 = eR + rr*625 + 4*jb;
    const float* e1 = eI + rr*625 + 4*jb;
    Psh[0][rr][jb] = (e0[0] + e0[1]) + (e0[2] + e0[3]);
    Psh[1][rr][jb] = (e1[0] + e1[1]) + (e1[2] + e1[3]);
  }
  __syncthreads();
  int bs1 = b*16 + s;        // watermarked
  int bs2 = b*16 + s + 8;    // original
  for (int t = tid; t < 2*156; t += 128){
    int half = t / 156, jb = t - half*156;
    float sum = ((Psh[half][0][jb] + Psh[half][1][jb]) +
                 (Psh[half][2][jb] + Psh[half][3][jb])) + Psh[half][4][jb];
    int bsx = half ? bs2 : bs1;
    d_P[((size_t)bsx*NBLK + jb)*NG2 + g] = sum;
  }
}

__global__ void k_red_all(){
  int idx = blockIdx.x*blockDim.x + threadIdx.x;
  if (idx < NBS*NBLK){
    const float* p = d_P + (size_t)idx*NG2;
    float sum = 0.f;
    #pragma unroll 4
    for (int i=0;i<NG2;i++) sum += p[i];
    d_blk[idx] = sum;
  }
}

// diffs + softmax(diff).diff in one block (diff array in shared)
__global__ void __launch_bounds__(1024) k_final(float* __restrict__ out){
  __shared__ float sdiff[NDIFF];
  __shared__ float redA[32];
  __shared__ float redB[32];
  int tid = threadIdx.x;
  for (int t = tid; t < NDIFF; t += 1024){
    int s = t / (8*NCH);
    int rem = t - s*(8*NCH);
    int b = rem / NCH, jb = rem - b*NCH;
    float ew = d_blk[(b*16+s)*NBLK + jb]   + d_blk[(b*16+s)*NBLK + jb + 1];
    float eo = d_blk[(b*16+s+8)*NBLK + jb] + d_blk[(b*16+s+8)*NBLK + jb + 1];
    float lw = 10.f*log10f(ew*(1.f/2048.f) + 1e-12f);
    float lo = 10.f*log10f(eo*(1.f/2048.f) + 1e-12f);
    sdiff[t] = lw - lo;
  }
  __syncthreads();
  float m = -1e30f;
  for (int i = tid; i < NDIFF; i += 1024) m = fmaxf(m, sdiff[i]);
  #pragma unroll
  for (int o = 16; o; o >>= 1) m = fmaxf(m, __shfl_xor_sync(~0u, m, o));
  if ((tid & 31) == 0) redA[tid >> 5] = m;
  __syncthreads();
  {
    float v = redA[tid & 31];
    #pragma unroll
    for (int o = 16; o; o >>= 1) v = fmaxf(v, __shfl_xor_sync(~0u, v, o));
    m = v;                              // full max in every thread
  }
  __syncthreads();
  float se = 0.f, sw = 0.f;
  for (int i = tid; i < NDIFF; i += 1024){
    float d = sdiff[i];
    float e = expf(d - m);
    se += e;
    sw = fmaf(e, d, sw);
  }
  #pragma unroll
  for (int o = 16; o; o >>= 1){
    se += __shfl_xor_sync(~0u, se, o);
    sw += __shfl_xor_sync(~0u, sw, o);
  }
  if ((tid & 31) == 0){ redA[tid >> 5] = se; redB[tid >> 5] = sw; }
  __syncthreads();
  if (tid == 0){
    float s1 = 0.f, s2 = 0.f;
    #pragma unroll
    for (int i = 0; i < 32; i++){ s1 += redA[i]; s2 += redB[i]; }
    out[0] = s2 / s1;
  }
}

extern "C" void kernel_launch(void* const* d_in, const int* in_sizes, int n_in,
                              void* d_out, int out_size){
  const float* xw = (const float*)d_in[0];
  const float* xo = (const float*)d_in[1];
  float* out = (float*)d_out;

  k_genW<<<(LTOT+255)/256, 256>>>();
  k_fwd1<<<dim3(64,8), 512>>>(xw, xo);
  k_f2i1<<<dim3(157,8), 256>>>();          // fused fwd2 + inv1 (157*4 = 628 >= 625)
  k_inv2_all<<<dim3(NG2,NPIPE), 128>>>();  // 52*5 = 260 >= 256 n1 rows
  k_red_all<<<(NBS*NBLK+255)/256, 256>>>();
  k_final<<<1, 1024>>>(out);
}